// round 6
// baseline (speedup 1.0000x reference)
#include <cuda_runtime.h>
#include <cstdint>
#include <cstring>

#define BATCH 32
#define TT    512
#define NGATE 1024   // 4*H
#define HDIM  256
#define OUTW  512

// Scratch (static device globals — no allocation allowed)
__device__ float g_xg[(size_t)2 * BATCH * TT * NGATE];   // pre-activations (both dirs)
__device__ float g_h1[(size_t)BATCH * TT * OUTW];        // layer-0 output (fwd||bwd concat)

// ---------------- f32x2 helpers ----------------
__device__ __forceinline__ void ffma2(unsigned long long& d, unsigned long long a, unsigned long long b) {
    asm("fma.rn.f32x2 %0, %1, %2, %0;" : "+l"(d) : "l"(a), "l"(b));
}
__device__ __forceinline__ float fold2(unsigned long long v) {
    float2 f; memcpy(&f, &v, 8); return f.x + f.y;
}
__device__ __forceinline__ unsigned long long pack2(float lo, float hi) {
    unsigned long long u;
    asm("mov.b64 %0, {%1, %2};" : "=l"(u) : "f"(lo), "f"(hi));
    return u;
}

// ---------------------------------------------------------------------------
// Input projection GEMM (unchanged from R5 — passing):
// Tile 128(M) x 64(N) x 32(K-stage), 256 threads, 8m x 4n microtile,
// k-paired FFMA2, register double-buffered gmem prefetch.
// ---------------------------------------------------------------------------
__global__ __launch_bounds__(256, 1) void gemm_proj(
    const float* __restrict__ src, int K, int nst,
    const float* __restrict__ Wf, const float* __restrict__ bf,
    const float* __restrict__ Wb, const float* __restrict__ bb)
{
    const int dir = blockIdx.z;
    const float* __restrict__ W    = dir ? Wb : Wf;
    const float* __restrict__ bias = dir ? bb : bf;
    const int j0 = blockIdx.x * 64;
    const int r0 = blockIdx.y * 128;

    __shared__ __align__(16) float2 As2[2][16][128];
    __shared__ __align__(16) float2 Bs2[2][16][64];

    const int tid = threadIdx.x;

    const int arow  = tid >> 1;
    const int ahalf = tid & 1;
    const int brow  = tid & 63;
    const int bq    = tid >> 6;
    const float* aptr = src + (size_t)(r0 + arow) * K + ahalf * 16;
    const float* bptr = W   + (size_t)(j0 + brow) * K + bq * 8;

    const int wid  = tid >> 5;
    const int lane = tid & 31;
    const int mbase = (wid & 3) * 32 + (lane & 3) * 8;
    const int nbase = (wid >> 2) * 32 + (lane >> 2) * 4;

    unsigned long long acc[8][4];
    #pragma unroll
    for (int i = 0; i < 8; i++)
        #pragma unroll
        for (int u = 0; u < 4; u++) acc[i][u] = 0ull;

    float4 pa[4], pb[2];

    #pragma unroll
    for (int q = 0; q < 4; q++) pa[q] = *(const float4*)(aptr + q * 4);
    #pragma unroll
    for (int q = 0; q < 2; q++) pb[q] = *(const float4*)(bptr + q * 4);

    #pragma unroll
    for (int q = 0; q < 4; q++) {
        int kp = ahalf * 8 + q * 2;
        As2[0][kp    ][arow] = make_float2(pa[q].x, pa[q].y);
        As2[0][kp + 1][arow] = make_float2(pa[q].z, pa[q].w);
    }
    #pragma unroll
    for (int q = 0; q < 2; q++) {
        int kp = bq * 4 + q * 2;
        Bs2[0][kp    ][brow] = make_float2(pb[q].x, pb[q].y);
        Bs2[0][kp + 1][brow] = make_float2(pb[q].z, pb[q].w);
    }
    __syncthreads();

    int buf = 0;
    for (int s = 0; s < nst; ++s) {
        if (s + 1 < nst) {
            const float* ap = aptr + (size_t)(s + 1) * 32;
            const float* bp = bptr + (size_t)(s + 1) * 32;
            #pragma unroll
            for (int q = 0; q < 4; q++) pa[q] = *(const float4*)(ap + q * 4);
            #pragma unroll
            for (int q = 0; q < 2; q++) pb[q] = *(const float4*)(bp + q * 4);
        }

        #pragma unroll
        for (int kp = 0; kp < 16; ++kp) {
            ulonglong2 aA = *(const ulonglong2*)&As2[buf][kp][mbase    ];
            ulonglong2 aB = *(const ulonglong2*)&As2[buf][kp][mbase + 2];
            ulonglong2 aC = *(const ulonglong2*)&As2[buf][kp][mbase + 4];
            ulonglong2 aD = *(const ulonglong2*)&As2[buf][kp][mbase + 6];
            ulonglong2 bA = *(const ulonglong2*)&Bs2[buf][kp][nbase    ];
            ulonglong2 bB = *(const ulonglong2*)&Bs2[buf][kp][nbase + 2];
            unsigned long long av[8] = {aA.x, aA.y, aB.x, aB.y, aC.x, aC.y, aD.x, aD.y};
            unsigned long long bv[4] = {bA.x, bA.y, bB.x, bB.y};
            #pragma unroll
            for (int i = 0; i < 8; i++) {
                ffma2(acc[i][0], av[i], bv[0]);
                ffma2(acc[i][1], av[i], bv[1]);
                ffma2(acc[i][2], av[i], bv[2]);
                ffma2(acc[i][3], av[i], bv[3]);
            }
        }
        __syncthreads();

        if (s + 1 < nst) {
            const int nb = buf ^ 1;
            #pragma unroll
            for (int q = 0; q < 4; q++) {
                int kp = ahalf * 8 + q * 2;
                As2[nb][kp    ][arow] = make_float2(pa[q].x, pa[q].y);
                As2[nb][kp + 1][arow] = make_float2(pa[q].z, pa[q].w);
            }
            #pragma unroll
            for (int q = 0; q < 2; q++) {
                int kp = bq * 4 + q * 2;
                Bs2[nb][kp    ][brow] = make_float2(pb[q].x, pb[q].y);
                Bs2[nb][kp + 1][brow] = make_float2(pb[q].z, pb[q].w);
            }
            __syncthreads();
        }
        buf ^= 1;
    }

    float4 bv4 = *(const float4*)&bias[j0 + nbase];
    #pragma unroll
    for (int i = 0; i < 8; i++) {
        float4 o;
        o.x = fold2(acc[i][0]) + bv4.x;
        o.y = fold2(acc[i][1]) + bv4.y;
        o.z = fold2(acc[i][2]) + bv4.z;
        o.w = fold2(acc[i][3]) + bv4.w;
        *(float4*)(g_xg + ((size_t)dir * (BATCH * TT) + r0 + mbase + i) * NGATE + j0 + nbase) = o;
    }
}

// ---------------------------------------------------------------------------
// Recurrence v3: mbarrier handshake instead of per-step cluster barrier.
// full_mbar[b] on each CTA counts 256 arrivals (8 peer CTAs x 32 threads);
// each thread: st.shared::cluster.v4 push + mbarrier.arrive.release.cluster.
// Consumers try_wait.parity.acquire.cluster. Double buffer gives backpressure.
// ---------------------------------------------------------------------------
__device__ __forceinline__ float sigmoidf_(float x) { return 1.0f / (1.0f + __expf(-x)); }

__global__ __launch_bounds__(256, 1) __cluster_dims__(8, 1, 1)
void lstm_rec(const float* __restrict__ whhF, const float* __restrict__ whhB,
              float* __restrict__ out)
{
    __shared__ __align__(16) float h_s[2 * 1024];   // [2 buf][4 batch][256]
    __shared__ float g_s [512];
    __shared__ float rsum[512];
    __shared__ __align__(16) float hstage[128];
    __shared__ __align__(8) unsigned long long full_mbar[2];

    const int tid   = threadIdx.x;
    const int j     = tid & 127;
    const int kh    = tid >> 7;
    const int brank = blockIdx.x & 7;
    const int cid   = blockIdx.x >> 3;
    const int dir   = cid >> 3;
    const int bg    = cid & 7;
    const float* __restrict__ whh = dir ? whhB : whhF;

    const int gate = j >> 5;
    const int kl   = j & 31;
    const int grow = (gate << 8) + (brank << 5) + kl;

    unsigned long long Wreg[64];
    {
        const float* wrow = whh + (size_t)grow * HDIM + (kh << 7);
        #pragma unroll
        for (int q = 0; q < 64; ++q) {
            float2 w = *(const float2*)(wrow + 2 * q);
            memcpy(&Wreg[q], &w, 8);
        }
    }

    // local shared addresses (u32)
    uint32_t h_local, m_local;
    asm volatile("{ .reg .u64 t; cvta.to.shared.u64 t, %1; cvt.u32.u64 %0, t; }"
                 : "=r"(h_local) : "l"((const float*)h_s));
    asm volatile("{ .reg .u64 t; cvta.to.shared.u64 t, %1; cvt.u32.u64 %0, t; }"
                 : "=r"(m_local) : "l"((const unsigned long long*)full_mbar));

    // init mbarriers: 256 arrivals per phase (8 CTAs x 32 threads)
    if (tid == 0) {
        asm volatile("mbarrier.init.shared.b64 [%0], %1;" :: "r"(m_local),     "r"(256u) : "memory");
        asm volatile("mbarrier.init.shared.b64 [%0], %1;" :: "r"(m_local + 8), "r"(256u) : "memory");
    }
    if (tid < 128) hstage[tid] = 0.f;
    __syncthreads();
    // cluster-wide: all mbarriers initialized before any push/arrive
    asm volatile("barrier.cluster.arrive.aligned;\n\tbarrier.cluster.wait.aligned;" ::: "memory");

    // remote addresses for this thread's destination CTA (rank = tid>>5)
    uint32_t peer_h, peer_m;
    {
        uint32_t rk = (uint32_t)(tid >> 5);
        asm volatile("mapa.shared::cluster.u32 %0, %1, %2;" : "=r"(peer_h) : "r"(h_local), "r"(rk));
        asm volatile("mapa.shared::cluster.u32 %0, %1, %2;" : "=r"(peer_m) : "r"(m_local), "r"(rk));
    }
    const int i5 = tid & 31;
    const uint32_t push_off = ((uint32_t)(i5 >> 3) << 10) + ((uint32_t)brank << 7) + ((uint32_t)(i5 & 7) << 4);

    // seed buffer 0 with zeros through the normal push path
    {
        const float4 v = *(const float4*)&hstage[i5 << 2];   // zeros
        asm volatile("st.shared::cluster.v4.f32 [%0], {%1, %2, %3, %4};"
                     :: "r"(peer_h + push_off), "f"(v.x), "f"(v.y), "f"(v.z), "f"(v.w) : "memory");
        asm volatile("mbarrier.arrive.release.cluster.shared::cluster.b64 _, [%0];"
                     :: "r"(peer_m) : "memory");
    }

    const float* xgb = g_xg + (((size_t)dir * BATCH + bg * 4) * TT) * NGATE;

    float c_state = 0.f;
    int t = dir ? (TT - 1) : 0;
    const int tstep = dir ? -1 : 1;

    float x0 = 0.f, x1 = 0.f, x2 = 0.f, x3 = 0.f;
    if (kh == 0) {
        x0 = xgb[((size_t)0 * TT + t) * NGATE + grow];
        x1 = xgb[((size_t)1 * TT + t) * NGATE + grow];
        x2 = xgb[((size_t)2 * TT + t) * NGATE + grow];
        x3 = xgb[((size_t)3 * TT + t) * NGATE + grow];
    }

    int ph0 = 0, ph1 = 0;
    for (int it = 0; it < TT; ++it) {
        const int b = it & 1;
        // ---- wait for this buffer's 256 arrivals (acquire cluster) ----
        {
            const uint32_t mb = m_local + ((uint32_t)b << 3);
            const uint32_t par = (uint32_t)(b ? ph1 : ph0);
            uint32_t done;
            asm volatile(
                "{\n\t.reg .pred p;\n\t"
                "mbarrier.try_wait.parity.acquire.cluster.shared::cta.b64 p, [%1], %2, 0x989680;\n\t"
                "selp.b32 %0, 1, 0, p;\n\t}"
                : "=r"(done) : "r"(mb), "r"(par) : "memory");
            while (!done) {
                asm volatile(
                    "{\n\t.reg .pred p;\n\t"
                    "mbarrier.try_wait.parity.acquire.cluster.shared::cta.b64 p, [%1], %2, 0x989680;\n\t"
                    "selp.b32 %0, 1, 0, p;\n\t}"
                    : "=r"(done) : "r"(mb), "r"(par) : "memory");
            }
            if (b) ph1 ^= 1; else ph0 ^= 1;
        }

        unsigned long long acc0, acc1, acc2, acc3;
        if (kh == 0) {
            acc0 = pack2(x0, 0.f); acc1 = pack2(x1, 0.f);
            acc2 = pack2(x2, 0.f); acc3 = pack2(x3, 0.f);
        } else {
            acc0 = acc1 = acc2 = acc3 = 0ull;
        }

        const ulonglong2* hptr = reinterpret_cast<const ulonglong2*>(h_s + (b << 10) + (kh << 7));
        #pragma unroll
        for (int q = 0; q < 32; ++q) {
            ulonglong2 ha = hptr[q];
            ulonglong2 hb = hptr[q + 64];
            ulonglong2 hc = hptr[q + 128];
            ulonglong2 hd = hptr[q + 192];
            unsigned long long w0 = Wreg[2 * q], w1 = Wreg[2 * q + 1];
            ffma2(acc0, w0, ha.x); ffma2(acc1, w0, hb.x);
            ffma2(acc2, w0, hc.x); ffma2(acc3, w0, hd.x);
            ffma2(acc0, w1, ha.y); ffma2(acc1, w1, hb.y);
            ffma2(acc2, w1, hc.y); ffma2(acc3, w1, hd.y);
        }

        float s0 = fold2(acc0), s1 = fold2(acc1), s2 = fold2(acc2), s3 = fold2(acc3);
        if (kh == 0) {
            g_s[      j] = s0; g_s[128 + j] = s1; g_s[256 + j] = s2; g_s[384 + j] = s3;
        } else {
            rsum[      j] = s0; rsum[128 + j] = s1; rsum[256 + j] = s2; rsum[384 + j] = s3;
        }
        __syncthreads();

        float hval = 0.f;
        if (tid < 128) {
            const int bb   = tid >> 5;
            const int kloc = tid & 31;
            const int base = bb * 128 + kloc;
            float gi = g_s[base     ] + rsum[base     ];
            float gf = g_s[base + 32] + rsum[base + 32];
            float gg = g_s[base + 64] + rsum[base + 64];
            float go = g_s[base + 96] + rsum[base + 96];
            float i_ = sigmoidf_(gi);
            float f_ = sigmoidf_(gf);
            float g_ = tanhf(gg);
            float o_ = sigmoidf_(go);
            c_state = f_ * c_state + i_ * g_;
            hval = o_ * tanhf(c_state);
            hstage[tid] = hval;
        }
        __syncthreads();

        // ---- push h to peer's other buffer + arrive on its mbar ----
        {
            const float4 v = *(const float4*)&hstage[i5 << 2];
            const uint32_t dst = peer_h + ((uint32_t)(b ^ 1) << 12) + push_off;
            asm volatile("st.shared::cluster.v4.f32 [%0], {%1, %2, %3, %4};"
                         :: "r"(dst), "f"(v.x), "f"(v.y), "f"(v.z), "f"(v.w) : "memory");
            asm volatile("mbarrier.arrive.release.cluster.shared::cluster.b64 _, [%0];"
                         :: "r"(peer_m + ((uint32_t)(b ^ 1) << 3)) : "memory");
        }

        // fire-and-forget output store + next-x prefetch (no drain needed now)
        if (tid < 128) {
            const int bb   = tid >> 5;
            const int kloc = tid & 31;
            out[(((size_t)(bg * 4 + bb)) * TT + t) * OUTW + (dir << 8) + (brank << 5) + kloc] = hval;
        }
        if (kh == 0 && it + 1 < TT) {
            const int tnx = t + tstep;
            x0 = xgb[((size_t)0 * TT + tnx) * NGATE + grow];
            x1 = xgb[((size_t)1 * TT + tnx) * NGATE + grow];
            x2 = xgb[((size_t)2 * TT + tnx) * NGATE + grow];
            x3 = xgb[((size_t)3 * TT + tnx) * NGATE + grow];
        }

        t += tstep;
    }

    // keep smem alive until all peers' final pushes have landed
    asm volatile("barrier.cluster.arrive.aligned;\n\tbarrier.cluster.wait.aligned;" ::: "memory");
}

// ---------------------------------------------------------------------------
extern "C" void kernel_launch(void* const* d_in, const int* in_sizes, int n_in,
                              void* d_out, int out_size)
{
    const float* x         = (const float*)d_in[0];
    const float* w_ih_l0f  = (const float*)d_in[1];
    const float* w_hh_l0f  = (const float*)d_in[2];
    const float* b_l0f     = (const float*)d_in[3];
    const float* w_ih_l0b  = (const float*)d_in[4];
    const float* w_hh_l0b  = (const float*)d_in[5];
    const float* b_l0b     = (const float*)d_in[6];
    const float* w_ih_l1f  = (const float*)d_in[7];
    const float* w_hh_l1f  = (const float*)d_in[8];
    const float* b_l1f     = (const float*)d_in[9];
    const float* w_ih_l1b  = (const float*)d_in[10];
    const float* w_hh_l1b  = (const float*)d_in[11];
    const float* b_l1b     = (const float*)d_in[12];
    float* out = (float*)d_out;

    float* h1 = nullptr;
    cudaGetSymbolAddress((void**)&h1, g_h1);

    dim3 ggrid(16, 128, 2);   // N/64, M/128, dirs

    // Layer 0 (K=256, 8 stages)
    gemm_proj<<<ggrid, 256>>>(x, 256, 8, w_ih_l0f, b_l0f, w_ih_l0b, b_l0b);
    lstm_rec<<<128, 256>>>(w_hh_l0f, w_hh_l0b, h1);

    // Layer 1 (K=512, 16 stages)
    gemm_proj<<<ggrid, 256>>>(h1, 512, 16, w_ih_l1f, b_l1f, w_ih_l1b, b_l1b);
    lstm_rec<<<128, 256>>>(w_hh_l1f, w_hh_l1b, out);
}

// round 7
// speedup vs baseline: 1.2545x; 1.2545x over previous
#include <cuda_runtime.h>
#include <cstdint>
#include <cstring>

#define BATCH 32
#define TT    512
#define NGATE 1024   // 4*H
#define HDIM  256
#define OUTW  512

// Scratch (static device globals — no allocation allowed)
__device__ float g_xg[(size_t)2 * BATCH * TT * NGATE];   // pre-activations (both dirs)
__device__ float g_h1[(size_t)BATCH * TT * OUTW];        // layer-0 output (fwd||bwd concat)

// ---------------- f32x2 helpers ----------------
__device__ __forceinline__ void ffma2(unsigned long long& d, unsigned long long a, unsigned long long b) {
    asm("fma.rn.f32x2 %0, %1, %2, %0;" : "+l"(d) : "l"(a), "l"(b));
}
__device__ __forceinline__ float fold2(unsigned long long v) {
    float2 f; memcpy(&f, &v, 8); return f.x + f.y;
}
__device__ __forceinline__ unsigned long long pack2(float lo, float hi) {
    unsigned long long u;
    asm("mov.b64 %0, {%1, %2};" : "=l"(u) : "f"(lo), "f"(hi));
    return u;
}

// ---------------------------------------------------------------------------
// Input projection GEMM (unchanged from R5 — passing):
// Tile 128(M) x 64(N) x 32(K-stage), 256 threads, 8m x 4n microtile,
// k-paired FFMA2, register double-buffered gmem prefetch.
// ---------------------------------------------------------------------------
__global__ __launch_bounds__(256, 1) void gemm_proj(
    const float* __restrict__ src, int K, int nst,
    const float* __restrict__ Wf, const float* __restrict__ bf,
    const float* __restrict__ Wb, const float* __restrict__ bb)
{
    const int dir = blockIdx.z;
    const float* __restrict__ W    = dir ? Wb : Wf;
    const float* __restrict__ bias = dir ? bb : bf;
    const int j0 = blockIdx.x * 64;
    const int r0 = blockIdx.y * 128;

    __shared__ __align__(16) float2 As2[2][16][128];
    __shared__ __align__(16) float2 Bs2[2][16][64];

    const int tid = threadIdx.x;

    const int arow  = tid >> 1;
    const int ahalf = tid & 1;
    const int brow  = tid & 63;
    const int bq    = tid >> 6;
    const float* aptr = src + (size_t)(r0 + arow) * K + ahalf * 16;
    const float* bptr = W   + (size_t)(j0 + brow) * K + bq * 8;

    const int wid  = tid >> 5;
    const int lane = tid & 31;
    const int mbase = (wid & 3) * 32 + (lane & 3) * 8;
    const int nbase = (wid >> 2) * 32 + (lane >> 2) * 4;

    unsigned long long acc[8][4];
    #pragma unroll
    for (int i = 0; i < 8; i++)
        #pragma unroll
        for (int u = 0; u < 4; u++) acc[i][u] = 0ull;

    float4 pa[4], pb[2];

    #pragma unroll
    for (int q = 0; q < 4; q++) pa[q] = *(const float4*)(aptr + q * 4);
    #pragma unroll
    for (int q = 0; q < 2; q++) pb[q] = *(const float4*)(bptr + q * 4);

    #pragma unroll
    for (int q = 0; q < 4; q++) {
        int kp = ahalf * 8 + q * 2;
        As2[0][kp    ][arow] = make_float2(pa[q].x, pa[q].y);
        As2[0][kp + 1][arow] = make_float2(pa[q].z, pa[q].w);
    }
    #pragma unroll
    for (int q = 0; q < 2; q++) {
        int kp = bq * 4 + q * 2;
        Bs2[0][kp    ][brow] = make_float2(pb[q].x, pb[q].y);
        Bs2[0][kp + 1][brow] = make_float2(pb[q].z, pb[q].w);
    }
    __syncthreads();

    int buf = 0;
    for (int s = 0; s < nst; ++s) {
        if (s + 1 < nst) {
            const float* ap = aptr + (size_t)(s + 1) * 32;
            const float* bp = bptr + (size_t)(s + 1) * 32;
            #pragma unroll
            for (int q = 0; q < 4; q++) pa[q] = *(const float4*)(ap + q * 4);
            #pragma unroll
            for (int q = 0; q < 2; q++) pb[q] = *(const float4*)(bp + q * 4);
        }

        #pragma unroll
        for (int kp = 0; kp < 16; ++kp) {
            ulonglong2 aA = *(const ulonglong2*)&As2[buf][kp][mbase    ];
            ulonglong2 aB = *(const ulonglong2*)&As2[buf][kp][mbase + 2];
            ulonglong2 aC = *(const ulonglong2*)&As2[buf][kp][mbase + 4];
            ulonglong2 aD = *(const ulonglong2*)&As2[buf][kp][mbase + 6];
            ulonglong2 bA = *(const ulonglong2*)&Bs2[buf][kp][nbase    ];
            ulonglong2 bB = *(const ulonglong2*)&Bs2[buf][kp][nbase + 2];
            unsigned long long av[8] = {aA.x, aA.y, aB.x, aB.y, aC.x, aC.y, aD.x, aD.y};
            unsigned long long bv[4] = {bA.x, bA.y, bB.x, bB.y};
            #pragma unroll
            for (int i = 0; i < 8; i++) {
                ffma2(acc[i][0], av[i], bv[0]);
                ffma2(acc[i][1], av[i], bv[1]);
                ffma2(acc[i][2], av[i], bv[2]);
                ffma2(acc[i][3], av[i], bv[3]);
            }
        }
        __syncthreads();

        if (s + 1 < nst) {
            const int nb = buf ^ 1;
            #pragma unroll
            for (int q = 0; q < 4; q++) {
                int kp = ahalf * 8 + q * 2;
                As2[nb][kp    ][arow] = make_float2(pa[q].x, pa[q].y);
                As2[nb][kp + 1][arow] = make_float2(pa[q].z, pa[q].w);
            }
            #pragma unroll
            for (int q = 0; q < 2; q++) {
                int kp = bq * 4 + q * 2;
                Bs2[nb][kp    ][brow] = make_float2(pb[q].x, pb[q].y);
                Bs2[nb][kp + 1][brow] = make_float2(pb[q].z, pb[q].w);
            }
            __syncthreads();
        }
        buf ^= 1;
    }

    float4 bv4 = *(const float4*)&bias[j0 + nbase];
    #pragma unroll
    for (int i = 0; i < 8; i++) {
        float4 o;
        o.x = fold2(acc[i][0]) + bv4.x;
        o.y = fold2(acc[i][1]) + bv4.y;
        o.z = fold2(acc[i][2]) + bv4.z;
        o.w = fold2(acc[i][3]) + bv4.w;
        *(float4*)(g_xg + ((size_t)dir * (BATCH * TT) + r0 + mbase + i) * NGATE + j0 + nbase) = o;
    }
}

// ---------------------------------------------------------------------------
// Recurrence v4: st.async + tx-count mbarrier. No cluster barriers in loop,
// no per-thread arrives — each 16B h push carries its own complete_tx.
// mbar[b] (count=1) expects 4096 B/phase (8 CTAs x 512 B).
// ---------------------------------------------------------------------------
__device__ __forceinline__ float sigmoid_fast(float x) {
    return __fdividef(1.f, 1.f + __expf(-x));
}
__device__ __forceinline__ float tanh_fast(float x) {
    float xc = fminf(fmaxf(x, -15.f), 15.f);
    float e = __expf(2.f * xc);
    return __fdividef(e - 1.f, e + 1.f);
}

__global__ __launch_bounds__(256, 1) __cluster_dims__(8, 1, 1)
void lstm_rec(const float* __restrict__ whhF, const float* __restrict__ whhB,
              float* __restrict__ out)
{
    __shared__ __align__(16) float h_s[2 * 1024];   // [2 buf][4 batch][256]
    __shared__ float g_s [512];
    __shared__ float rsum[512];
    __shared__ __align__(16) float hstage[128];
    __shared__ __align__(8) unsigned long long full_mbar[2];

    const int tid   = threadIdx.x;
    const int j     = tid & 127;
    const int kh    = tid >> 7;
    const int brank = blockIdx.x & 7;
    const int cid   = blockIdx.x >> 3;
    const int dir   = cid >> 3;
    const int bg    = cid & 7;
    const float* __restrict__ whh = dir ? whhB : whhF;

    const int gate = j >> 5;
    const int kl   = j & 31;
    const int grow = (gate << 8) + (brank << 5) + kl;

    unsigned long long Wreg[64];
    {
        const float* wrow = whh + (size_t)grow * HDIM + (kh << 7);
        #pragma unroll
        for (int q = 0; q < 64; ++q) {
            float2 w = *(const float2*)(wrow + 2 * q);
            memcpy(&Wreg[q], &w, 8);
        }
    }

    uint32_t h_local, m_local;
    asm volatile("{ .reg .u64 t; cvta.to.shared.u64 t, %1; cvt.u32.u64 %0, t; }"
                 : "=r"(h_local) : "l"((const float*)h_s));
    asm volatile("{ .reg .u64 t; cvta.to.shared.u64 t, %1; cvt.u32.u64 %0, t; }"
                 : "=r"(m_local) : "l"((const unsigned long long*)full_mbar));

    // init: count=1 per mbar (single expect_tx arrive per phase)
    if (tid == 0) {
        asm volatile("mbarrier.init.shared.b64 [%0], %1;" :: "r"(m_local),     "r"(1u) : "memory");
        asm volatile("mbarrier.init.shared.b64 [%0], %1;" :: "r"(m_local + 8), "r"(1u) : "memory");
    }
    if (tid < 128) hstage[tid] = 0.f;
    __syncthreads();
    // post phase-0 expects BEFORE any peer can push (separated by cluster.sync)
    if (tid == 0) {
        asm volatile("mbarrier.arrive.expect_tx.shared.b64 _, [%0], %1;"
                     :: "r"(m_local),     "r"(4096u) : "memory");
        asm volatile("mbarrier.arrive.expect_tx.shared.b64 _, [%0], %1;"
                     :: "r"(m_local + 8), "r"(4096u) : "memory");
    }
    __syncthreads();
    asm volatile("barrier.cluster.arrive.aligned;\n\tbarrier.cluster.wait.aligned;" ::: "memory");

    // remote addresses for this thread's destination CTA (rank = tid>>5)
    uint32_t peer_h, peer_m;
    {
        uint32_t rk = (uint32_t)(tid >> 5);
        asm volatile("mapa.shared::cluster.u32 %0, %1, %2;" : "=r"(peer_h) : "r"(h_local), "r"(rk));
        asm volatile("mapa.shared::cluster.u32 %0, %1, %2;" : "=r"(peer_m) : "r"(m_local), "r"(rk));
    }
    const int i5 = tid & 31;
    const uint32_t push_off = ((uint32_t)(i5 >> 3) << 10) + ((uint32_t)brank << 7) + ((uint32_t)(i5 & 7) << 4);

    // seed buffer 0 with zeros via the normal st.async path
    {
        const float4 v = *(const float4*)&hstage[i5 << 2];   // zeros
        asm volatile("st.async.shared::cluster.mbarrier::complete_tx::bytes.v4.f32 "
                     "[%0], {%1, %2, %3, %4}, [%5];"
                     :: "r"(peer_h + push_off), "f"(v.x), "f"(v.y), "f"(v.z), "f"(v.w),
                        "r"(peer_m) : "memory");
    }

    const float* xgb = g_xg + (((size_t)dir * BATCH + bg * 4) * TT) * NGATE;

    float c_state = 0.f;
    int t = dir ? (TT - 1) : 0;
    const int tstep = dir ? -1 : 1;

    float x0 = 0.f, x1 = 0.f, x2 = 0.f, x3 = 0.f;
    if (kh == 0) {
        x0 = xgb[((size_t)0 * TT + t) * NGATE + grow];
        x1 = xgb[((size_t)1 * TT + t) * NGATE + grow];
        x2 = xgb[((size_t)2 * TT + t) * NGATE + grow];
        x3 = xgb[((size_t)3 * TT + t) * NGATE + grow];
    }

    int ph0 = 0, ph1 = 0;
    for (int it = 0; it < TT; ++it) {
        const int b = it & 1;
        // ---- wait for this buffer's 4096 tx bytes ----
        {
            const uint32_t mb = m_local + ((uint32_t)b << 3);
            const uint32_t par = (uint32_t)(b ? ph1 : ph0);
            uint32_t done;
            asm volatile(
                "{\n\t.reg .pred p;\n\t"
                "mbarrier.try_wait.parity.acquire.cluster.shared::cta.b64 p, [%1], %2, 0x989680;\n\t"
                "selp.b32 %0, 1, 0, p;\n\t}"
                : "=r"(done) : "r"(mb), "r"(par) : "memory");
            while (!done) {
                asm volatile(
                    "{\n\t.reg .pred p;\n\t"
                    "mbarrier.try_wait.parity.acquire.cluster.shared::cta.b64 p, [%1], %2, 0x989680;\n\t"
                    "selp.b32 %0, 1, 0, p;\n\t}"
                    : "=r"(done) : "r"(mb), "r"(par) : "memory");
            }
            if (b) ph1 ^= 1; else ph0 ^= 1;
            // re-arm this mbar for its next use (it+2); pushes for it+2 exist iff it<=TT-2
            if (tid == 0 && it < TT - 1) {
                asm volatile("mbarrier.arrive.expect_tx.shared.b64 _, [%0], %1;"
                             :: "r"(mb), "r"(4096u) : "memory");
            }
        }

        unsigned long long acc0, acc1, acc2, acc3;
        if (kh == 0) {
            acc0 = pack2(x0, 0.f); acc1 = pack2(x1, 0.f);
            acc2 = pack2(x2, 0.f); acc3 = pack2(x3, 0.f);
        } else {
            acc0 = acc1 = acc2 = acc3 = 0ull;
        }

        const ulonglong2* hptr = reinterpret_cast<const ulonglong2*>(h_s + (b << 10) + (kh << 7));
        #pragma unroll
        for (int q = 0; q < 32; ++q) {
            ulonglong2 ha = hptr[q];
            ulonglong2 hb = hptr[q + 64];
            ulonglong2 hc = hptr[q + 128];
            ulonglong2 hd = hptr[q + 192];
            unsigned long long w0 = Wreg[2 * q], w1 = Wreg[2 * q + 1];
            ffma2(acc0, w0, ha.x); ffma2(acc1, w0, hb.x);
            ffma2(acc2, w0, hc.x); ffma2(acc3, w0, hd.x);
            ffma2(acc0, w1, ha.y); ffma2(acc1, w1, hb.y);
            ffma2(acc2, w1, hc.y); ffma2(acc3, w1, hd.y);
        }

        float s0 = fold2(acc0), s1 = fold2(acc1), s2 = fold2(acc2), s3 = fold2(acc3);
        if (kh == 0) {
            g_s[      j] = s0; g_s[128 + j] = s1; g_s[256 + j] = s2; g_s[384 + j] = s3;
        } else {
            rsum[      j] = s0; rsum[128 + j] = s1; rsum[256 + j] = s2; rsum[384 + j] = s3;
        }
        __syncthreads();

        float hval = 0.f;
        if (tid < 128) {
            const int bb   = tid >> 5;
            const int kloc = tid & 31;
            const int base = bb * 128 + kloc;
            float gi = g_s[base     ] + rsum[base     ];
            float gf = g_s[base + 32] + rsum[base + 32];
            float gg = g_s[base + 64] + rsum[base + 64];
            float go = g_s[base + 96] + rsum[base + 96];
            float i_ = sigmoid_fast(gi);
            float f_ = sigmoid_fast(gf);
            float g_ = tanh_fast(gg);
            float o_ = sigmoid_fast(go);
            c_state = f_ * c_state + i_ * g_;
            hval = o_ * tanh_fast(c_state);
            hstage[tid] = hval;
        }
        __syncthreads();

        // ---- push h(it) into peers' buffer b^1 via st.async (self-completing) ----
        {
            const float4 v = *(const float4*)&hstage[i5 << 2];
            const uint32_t dst = peer_h + ((uint32_t)(b ^ 1) << 12) + push_off;
            asm volatile("st.async.shared::cluster.mbarrier::complete_tx::bytes.v4.f32 "
                         "[%0], {%1, %2, %3, %4}, [%5];"
                         :: "r"(dst), "f"(v.x), "f"(v.y), "f"(v.z), "f"(v.w),
                            "r"(peer_m + ((uint32_t)(b ^ 1) << 3)) : "memory");
        }

        // fire-and-forget output store + next-x prefetch
        if (tid < 128) {
            const int bb   = tid >> 5;
            const int kloc = tid & 31;
            out[(((size_t)(bg * 4 + bb)) * TT + t) * OUTW + (dir << 8) + (brank << 5) + kloc] = hval;
        }
        if (kh == 0 && it + 1 < TT) {
            const int tnx = t + tstep;
            x0 = xgb[((size_t)0 * TT + tnx) * NGATE + grow];
            x1 = xgb[((size_t)1 * TT + tnx) * NGATE + grow];
            x2 = xgb[((size_t)2 * TT + tnx) * NGATE + grow];
            x3 = xgb[((size_t)3 * TT + tnx) * NGATE + grow];
        }

        t += tstep;
    }

    // consume final incoming pushes (end of it=TT-1 land in mbar[TT&1]=mbar[0]),
    // so no st.async targeting this CTA is in flight at exit
    {
        const uint32_t mb = m_local;   // buffer 0
        const uint32_t par = (uint32_t)ph0;
        uint32_t done;
        asm volatile(
            "{\n\t.reg .pred p;\n\t"
            "mbarrier.try_wait.parity.acquire.cluster.shared::cta.b64 p, [%1], %2, 0x989680;\n\t"
            "selp.b32 %0, 1, 0, p;\n\t}"
            : "=r"(done) : "r"(mb), "r"(par) : "memory");
        while (!done) {
            asm volatile(
                "{\n\t.reg .pred p;\n\t"
                "mbarrier.try_wait.parity.acquire.cluster.shared::cta.b64 p, [%1], %2, 0x989680;\n\t"
                "selp.b32 %0, 1, 0, p;\n\t}"
                : "=r"(done) : "r"(mb), "r"(par) : "memory");
        }
    }
    asm volatile("barrier.cluster.arrive.aligned;\n\tbarrier.cluster.wait.aligned;" ::: "memory");
}

// ---------------------------------------------------------------------------
extern "C" void kernel_launch(void* const* d_in, const int* in_sizes, int n_in,
                              void* d_out, int out_size)
{
    const float* x         = (const float*)d_in[0];
    const float* w_ih_l0f  = (const float*)d_in[1];
    const float* w_hh_l0f  = (const float*)d_in[2];
    const float* b_l0f     = (const float*)d_in[3];
    const float* w_ih_l0b  = (const float*)d_in[4];
    const float* w_hh_l0b  = (const float*)d_in[5];
    const float* b_l0b     = (const float*)d_in[6];
    const float* w_ih_l1f  = (const float*)d_in[7];
    const float* w_hh_l1f  = (const float*)d_in[8];
    const float* b_l1f     = (const float*)d_in[9];
    const float* w_ih_l1b  = (const float*)d_in[10];
    const float* w_hh_l1b  = (const float*)d_in[11];
    const float* b_l1b     = (const float*)d_in[12];
    float* out = (float*)d_out;

    float* h1 = nullptr;
    cudaGetSymbolAddress((void**)&h1, g_h1);

    dim3 ggrid(16, 128, 2);   // N/64, M/128, dirs

    // Layer 0 (K=256, 8 stages)
    gemm_proj<<<ggrid, 256>>>(x, 256, 8, w_ih_l0f, b_l0f, w_ih_l0b, b_l0b);
    lstm_rec<<<128, 256>>>(w_hh_l0f, w_hh_l0b, h1);

    // Layer 1 (K=512, 16 stages)
    gemm_proj<<<ggrid, 256>>>(h1, 512, 16, w_ih_l1f, b_l1f, w_ih_l1b, b_l1b);
    lstm_rec<<<128, 256>>>(w_hh_l1f, w_hh_l1b, out);
}